// round 14
// baseline (speedup 1.0000x reference)
#include <cuda_runtime.h>
#include <cuda_fp16.h>
#include <cstdint>

#define BB 4
#define CC 64
#define FD 50000
#define KN 16
#define BN_EPS 1e-5f

#define GEMM_TILES 391      // (FD+127)/128
#define GTILES 782          // (FD+63)/64
#define NORM_CHUNKS 6250    // FD/8

__device__ __half g_buf[BB * FD * CC];   // g[b][f][o] fp16
__device__ __half g_yt[BB * CC * FD];    // y_t[b][c][f] fp16
__device__ float g_sum[CC];
__device__ float g_sq[CC];

// ---------------------------------------------------------------------------
__device__ __forceinline__ uint32_t smem_u32(const void* p) {
    uint32_t a;
    asm("{ .reg .u64 t; cvta.to.shared.u64 t, %1; cvt.u32.u64 %0, t; }"
        : "=r"(a) : "l"(p));
    return a;
}
__device__ __forceinline__ void ldsm_x4(uint32_t& r0, uint32_t& r1,
                                        uint32_t& r2, uint32_t& r3, uint32_t addr) {
    asm volatile("ldmatrix.sync.aligned.m8n8.x4.shared.b16 {%0,%1,%2,%3}, [%4];"
                 : "=r"(r0), "=r"(r1), "=r"(r2), "=r"(r3) : "r"(addr));
}
__device__ __forceinline__ void ldsm_x4_trans(uint32_t& r0, uint32_t& r1,
                                              uint32_t& r2, uint32_t& r3, uint32_t addr) {
    asm volatile("ldmatrix.sync.aligned.m8n8.x4.trans.shared.b16 {%0,%1,%2,%3}, [%4];"
                 : "=r"(r0), "=r"(r1), "=r"(r2), "=r"(r3) : "r"(addr));
}
__device__ __forceinline__ void mma16816(float* c, uint32_t a0, uint32_t a1,
                                         uint32_t a2, uint32_t a3,
                                         uint32_t b0, uint32_t b1) {
    asm volatile(
        "mma.sync.aligned.m16n8k16.row.col.f32.f16.f16.f32 "
        "{%0,%1,%2,%3}, {%4,%5,%6,%7}, {%8,%9}, {%0,%1,%2,%3};"
        : "+f"(c[0]), "+f"(c[1]), "+f"(c[2]), "+f"(c[3])
        : "r"(a0), "r"(a1), "r"(a2), "r"(a3), "r"(b0), "r"(b1));
}

// ---------------------------------------------------------------------------
// GEMM via mma.sync (R10, proven): D[128f][64o] = A[128f][64c] * W[64o][64c]^T
#define SPA 136  // sA row stride halves (272B == 16 mod 128)
#define SPB 72   // sB row stride halves (144B == 16 mod 128)
__global__ __launch_bounds__(256)
void gemm_kernel(const float* __restrict__ fea, const float* __restrict__ W) {
    __shared__ __align__(16) __half sA[64 * SPA];  // [c][f]
    __shared__ __align__(16) __half sB[64 * SPB];  // [o][c]

    const int b = blockIdx.y;
    const int f0 = blockIdx.x * 128;
    const int t = threadIdx.x;
    const int wid = t >> 5, lane = t & 31;

    // stats zeroing: race-free here (kernel boundary orders gemm before gather)
    if (f0 == 0 && b == 0 && t < CC) { g_sum[t] = 0.f; g_sq[t] = 0.f; }

    // stage B = W [64o][64c] fp16 padded rows
    {
        const int o = t >> 2, q = t & 3;
        union { __half2 h2[8]; uint4 u[2]; } pk;
#pragma unroll
        for (int i = 0; i < 4; i++) {
            float4 wv = *(const float4*)(W + o * CC + q * 16 + 4 * i);
            pk.h2[2 * i]     = __floats2half2_rn(wv.x, wv.y);
            pk.h2[2 * i + 1] = __floats2half2_rn(wv.z, wv.w);
        }
        uint4* dst = (uint4*)(sB + o * SPB + q * 16);
        dst[0] = pk.u[0];
        dst[1] = pk.u[1];
    }
    // stage A = fea tile [64c][128f] fp16 as-is
    const float* feab = fea + (size_t)b * (CC * FD);
    const int nv = min(128, FD - f0);
    {
        const int c = t >> 2, q = t & 3;
        const float* src = feab + c * FD + f0 + q * 32;
        __half* dstrow = sA + c * SPA + q * 32;
#pragma unroll
        for (int i = 0; i < 8; i++) {
            float4 v = make_float4(0.f, 0.f, 0.f, 0.f);
            if (q * 32 + 4 * i + 3 < nv) v = *(const float4*)(src + 4 * i);
            union { __half2 h2[2]; unsigned long long u; } pk;
            pk.h2[0] = __floats2half2_rn(v.x, v.y);
            pk.h2[1] = __floats2half2_rn(v.z, v.w);
            *(unsigned long long*)(dstrow + 4 * i) = pk.u;
        }
    }
    __syncthreads();

    const uint32_t aBase = smem_u32(sA);
    const uint32_t bBase = smem_u32(sB);
    const int m0 = wid * 16;
    const int g = lane >> 3, r = lane & 7;
    const uint32_t aKoff = (g >> 1) * 8 + r;
    const uint32_t aMcol = m0 + (g & 1) * 8;
    const uint32_t bRowOff = (lane >> 4) * 8 + (lane & 7);
    const uint32_t bColOff = ((lane >> 3) & 1) * 8;

    float acc[8][4];
#pragma unroll
    for (int j = 0; j < 8; j++)
#pragma unroll
        for (int m = 0; m < 4; m++) acc[j][m] = 0.f;

#pragma unroll
    for (int kk = 0; kk < 4; kk++) {
        uint32_t a0, a1, a2, a3;
        ldsm_x4_trans(a0, a1, a2, a3,
                      aBase + ((kk * 16 + aKoff) * SPA + aMcol) * 2);
#pragma unroll
        for (int j = 0; j < 4; j++) {
            uint32_t b0, b1, b2, b3;
            ldsm_x4(b0, b1, b2, b3,
                    bBase + ((16 * j + bRowOff) * SPB + kk * 16 + bColOff) * 2);
            mma16816(acc[2 * j],     a0, a1, a2, a3, b0, b1);
            mma16816(acc[2 * j + 1], a0, a1, a2, a3, b2, b3);
        }
    }

    const int fr = f0 + m0 + (lane >> 2);
    const int colq = 2 * (lane & 3);
    __half* gb = g_buf + (size_t)b * (FD * CC);
    if (fr < FD) {
        __half* row = gb + (size_t)fr * CC;
#pragma unroll
        for (int j = 0; j < 8; j++)
            *(__half2*)(row + 8 * j + colq) = __floats2half2_rn(acc[j][0], acc[j][1]);
    }
    if (fr + 8 < FD) {
        __half* row = gb + (size_t)(fr + 8) * CC;
#pragma unroll
        for (int j = 0; j < 8; j++)
            *(__half2*)(row + 8 * j + colq) = __floats2half2_rn(acc[j][2], acc[j][3]);
    }
}

// ---------------------------------------------------------------------------
// Gather + bias + stats + TRANSPOSE: writes y_t[b][c][f] fp16 (coalesced).
// 64-face tiles; warp handles 8 faces; lane owns channels (2l, 2l+1).
__global__ __launch_bounds__(256) void gather_kernel(const int* __restrict__ ring,
                                                     const float* __restrict__ bias,
                                                     float* __restrict__ dummy) {
    __shared__ float tile[64][65];      // y fp32 [f_local][c]
    __shared__ float ssum[CC];
    __shared__ float ssq[CC];

    const int t = threadIdx.x;
    const int wid = t >> 5, lane = t & 31;
    const int b = blockIdx.y;
    const int f0 = blockIdx.x * 64;

    if (t < CC) { ssum[t] = 0.f; ssq[t] = 0.f; }
    __syncthreads();

    const __half2* gb = (const __half2*)(g_buf + (size_t)b * (FD * CC));
    const float bias0 = bias[2 * lane];
    const float bias1 = bias[2 * lane + 1];
    float s0 = 0.f, s1 = 0.f, q0 = 0.f, q1 = 0.f;

#pragma unroll
    for (int i = 0; i < 8; i++) {
        int f = f0 + wid * 8 + i;
        if (f >= FD) continue;
        const int* rp = ring + ((long long)(b * FD + f)) * KN;
        int myidx = (lane < KN) ? rp[lane] : 0;
        if ((unsigned)myidx >= (unsigned)FD) myidx = 0;   // defensive
        float accx = 0.f, accy = 0.f;
#pragma unroll
        for (int k = 0; k < KN; k++) {
            int idx = __shfl_sync(0xffffffffu, myidx, k);
            float2 v = __half22float2(gb[(size_t)idx * 32 + lane]);
            accx += v.x;
            accy += v.y;
        }
        float y0 = accx + bias0;
        float y1 = accy + bias1;
        tile[wid * 8 + i][2 * lane]     = y0;
        tile[wid * 8 + i][2 * lane + 1] = y1;
        s0 += y0; q0 += y0 * y0;
        s1 += y1; q1 += y1 * y1;
    }

    atomicAdd(&ssum[2 * lane],     s0);
    atomicAdd(&ssum[2 * lane + 1], s1);
    atomicAdd(&ssq[2 * lane],      q0);
    atomicAdd(&ssq[2 * lane + 1],  q1);
    __syncthreads();

    // transposed coalesced fp16 write: y_t[b][c][f0 + 2*lane, +1]
    {
        const int ff = f0 + 2 * lane;
        if (ff + 1 < FD) {
            for (int c = wid; c < CC; c += 8) {
                __half2 hv = __floats2half2_rn(tile[2 * lane][c],
                                               tile[2 * lane + 1][c]);
                *(__half2*)(g_yt + ((size_t)(b * CC + c)) * FD + ff) = hv;
            }
        }
    }

    if (t < CC) {
        atomicAdd(&g_sum[t], ssum[t]);
        atomicAdd(&g_sq[t],  ssq[t]);
    }
}

// ---------------------------------------------------------------------------
// Streaming norm: read y_t fp16 [b][c][f], normalize+ReLU, write out fp32.
// Thread handles 8 consecutive faces: 1 LDG.128 -> 8 FMA/ReLU -> 2 STG.128.
__global__ __launch_bounds__(256) void norm_kernel(const float* __restrict__ gamma,
                                                   const float* __restrict__ beta,
                                                   float* __restrict__ out) {
    const int id = blockIdx.x * 256 + threadIdx.x;
    const int b = id / (CC * NORM_CHUNKS);
    const int rem = id % (CC * NORM_CHUNKS);
    const int c = rem / NORM_CHUNKS;
    const int f0 = (rem % NORM_CHUNKS) * 8;

    const float inv_n = 1.0f / (float)(BB * FD);
    const float mean = g_sum[c] * inv_n;
    const float var  = g_sq[c] * inv_n - mean * mean;
    const float sc = gamma[c] * rsqrtf(var + BN_EPS);
    const float sh = beta[c] - mean * sc;

    const size_t base = ((size_t)(b * CC + c)) * FD + f0;
    uint4 v = *(const uint4*)(g_yt + base);
    const __half2* hp = (const __half2*)&v;
    float4 o0, o1;
    float2 p;
    p = __half22float2(hp[0]);
    o0.x = fmaxf(fmaf(p.x, sc, sh), 0.f); o0.y = fmaxf(fmaf(p.y, sc, sh), 0.f);
    p = __half22float2(hp[1]);
    o0.z = fmaxf(fmaf(p.x, sc, sh), 0.f); o0.w = fmaxf(fmaf(p.y, sc, sh), 0.f);
    p = __half22float2(hp[2]);
    o1.x = fmaxf(fmaf(p.x, sc, sh), 0.f); o1.y = fmaxf(fmaf(p.y, sc, sh), 0.f);
    p = __half22float2(hp[3]);
    o1.z = fmaxf(fmaf(p.x, sc, sh), 0.f); o1.w = fmaxf(fmaf(p.y, sc, sh), 0.f);
    ((float4*)(out + base))[0] = o0;
    ((float4*)(out + base))[1] = o1;
}

// ---------------------------------------------------------------------------
extern "C" void kernel_launch(void* const* d_in, const int* in_sizes, int n_in,
                              void* d_out, int out_size) {
    const float* fea   = (const float*)d_in[0];      // [B, C_in, F]
    const int*   ring  = (const int*)d_in[1];        // [B, F, K] int32
    const float* W     = (const float*)d_in[2];      // [C_out, C_in]
    const float* bias  = (const float*)d_in[3];      // [C_out]
    const float* gamma = (const float*)d_in[4];      // [C_out]
    const float* beta  = (const float*)d_in[5];      // [C_out]
    float*       out   = (float*)d_out;              // [B, C_out, F]

    dim3 gg(GEMM_TILES, BB);
    gemm_kernel<<<gg, 256>>>(fea, W);

    dim3 gt(GTILES, BB);
    gather_kernel<<<gt, 256>>>(ring, bias, out);

    norm_kernel<<<(BB * CC * NORM_CHUNKS) / 256, 256>>>(gamma, beta, out);
}

// round 15
// speedup vs baseline: 1.0770x; 1.0770x over previous
#include <cuda_runtime.h>
#include <cuda_fp16.h>
#include <cstdint>

#define BB 4
#define CC 64
#define FD 50000
#define KN 16
#define BN_EPS 1e-5f

#define GEMM_TILES 391      // (FD+127)/128
#define GTILES 782          // (FD+63)/64
#define NORM_CHUNKS 6250    // FD/8

__device__ __half g_buf[BB * FD * CC];   // g[b][f][o] fp16
__device__ __half g_yt[BB * CC * FD];    // y_t[b][c][f] fp16
__device__ float g_sum[CC];
__device__ float g_sq[CC];

// ---------------------------------------------------------------------------
__device__ __forceinline__ uint32_t smem_u32(const void* p) {
    uint32_t a;
    asm("{ .reg .u64 t; cvta.to.shared.u64 t, %1; cvt.u32.u64 %0, t; }"
        : "=r"(a) : "l"(p));
    return a;
}
__device__ __forceinline__ void ldsm_x4(uint32_t& r0, uint32_t& r1,
                                        uint32_t& r2, uint32_t& r3, uint32_t addr) {
    asm volatile("ldmatrix.sync.aligned.m8n8.x4.shared.b16 {%0,%1,%2,%3}, [%4];"
                 : "=r"(r0), "=r"(r1), "=r"(r2), "=r"(r3) : "r"(addr));
}
__device__ __forceinline__ void ldsm_x4_trans(uint32_t& r0, uint32_t& r1,
                                              uint32_t& r2, uint32_t& r3, uint32_t addr) {
    asm volatile("ldmatrix.sync.aligned.m8n8.x4.trans.shared.b16 {%0,%1,%2,%3}, [%4];"
                 : "=r"(r0), "=r"(r1), "=r"(r2), "=r"(r3) : "r"(addr));
}
__device__ __forceinline__ void mma16816(float* c, uint32_t a0, uint32_t a1,
                                         uint32_t a2, uint32_t a3,
                                         uint32_t b0, uint32_t b1) {
    asm volatile(
        "mma.sync.aligned.m16n8k16.row.col.f32.f16.f16.f32 "
        "{%0,%1,%2,%3}, {%4,%5,%6,%7}, {%8,%9}, {%0,%1,%2,%3};"
        : "+f"(c[0]), "+f"(c[1]), "+f"(c[2]), "+f"(c[3])
        : "r"(a0), "r"(a1), "r"(a2), "r"(a3), "r"(b0), "r"(b1));
}

// ---------------------------------------------------------------------------
// GEMM via mma.sync (R10, proven): D[128f][64o] = A[128f][64c] * W[64o][64c]^T
#define SPA 136  // sA row stride halves (272B == 16 mod 128)
#define SPB 72   // sB row stride halves (144B == 16 mod 128)
__global__ __launch_bounds__(256)
void gemm_kernel(const float* __restrict__ fea, const float* __restrict__ W) {
    __shared__ __align__(16) __half sA[64 * SPA];  // [c][f]
    __shared__ __align__(16) __half sB[64 * SPB];  // [o][c]

    const int b = blockIdx.y;
    const int f0 = blockIdx.x * 128;
    const int t = threadIdx.x;
    const int wid = t >> 5, lane = t & 31;

    // stats zeroing: race-free (kernel boundary orders gemm before gather)
    if (f0 == 0 && b == 0 && t < CC) { g_sum[t] = 0.f; g_sq[t] = 0.f; }

    // stage B = W [64o][64c] fp16 padded rows
    {
        const int o = t >> 2, q = t & 3;
        union { __half2 h2[8]; uint4 u[2]; } pk;
#pragma unroll
        for (int i = 0; i < 4; i++) {
            float4 wv = *(const float4*)(W + o * CC + q * 16 + 4 * i);
            pk.h2[2 * i]     = __floats2half2_rn(wv.x, wv.y);
            pk.h2[2 * i + 1] = __floats2half2_rn(wv.z, wv.w);
        }
        uint4* dst = (uint4*)(sB + o * SPB + q * 16);
        dst[0] = pk.u[0];
        dst[1] = pk.u[1];
    }
    // stage A = fea tile [64c][128f] fp16 as-is
    const float* feab = fea + (size_t)b * (CC * FD);
    const int nv = min(128, FD - f0);
    {
        const int c = t >> 2, q = t & 3;
        const float* src = feab + c * FD + f0 + q * 32;
        __half* dstrow = sA + c * SPA + q * 32;
#pragma unroll
        for (int i = 0; i < 8; i++) {
            float4 v = make_float4(0.f, 0.f, 0.f, 0.f);
            if (q * 32 + 4 * i + 3 < nv) v = *(const float4*)(src + 4 * i);
            union { __half2 h2[2]; unsigned long long u; } pk;
            pk.h2[0] = __floats2half2_rn(v.x, v.y);
            pk.h2[1] = __floats2half2_rn(v.z, v.w);
            *(unsigned long long*)(dstrow + 4 * i) = pk.u;
        }
    }
    __syncthreads();

    const uint32_t aBase = smem_u32(sA);
    const uint32_t bBase = smem_u32(sB);
    const int m0 = wid * 16;
    const int g = lane >> 3, r = lane & 7;
    const uint32_t aKoff = (g >> 1) * 8 + r;
    const uint32_t aMcol = m0 + (g & 1) * 8;
    const uint32_t bRowOff = (lane >> 4) * 8 + (lane & 7);
    const uint32_t bColOff = ((lane >> 3) & 1) * 8;

    float acc[8][4];
#pragma unroll
    for (int j = 0; j < 8; j++)
#pragma unroll
        for (int m = 0; m < 4; m++) acc[j][m] = 0.f;

#pragma unroll
    for (int kk = 0; kk < 4; kk++) {
        uint32_t a0, a1, a2, a3;
        ldsm_x4_trans(a0, a1, a2, a3,
                      aBase + ((kk * 16 + aKoff) * SPA + aMcol) * 2);
#pragma unroll
        for (int j = 0; j < 4; j++) {
            uint32_t b0, b1, b2, b3;
            ldsm_x4(b0, b1, b2, b3,
                    bBase + ((16 * j + bRowOff) * SPB + kk * 16 + bColOff) * 2);
            mma16816(acc[2 * j],     a0, a1, a2, a3, b0, b1);
            mma16816(acc[2 * j + 1], a0, a1, a2, a3, b2, b3);
        }
    }

    const int fr = f0 + m0 + (lane >> 2);
    const int colq = 2 * (lane & 3);
    __half* gb = g_buf + (size_t)b * (FD * CC);
    if (fr < FD) {
        __half* row = gb + (size_t)fr * CC;
#pragma unroll
        for (int j = 0; j < 8; j++)
            *(__half2*)(row + 8 * j + colq) = __floats2half2_rn(acc[j][0], acc[j][1]);
    }
    if (fr + 8 < FD) {
        __half* row = gb + (size_t)(fr + 8) * CC;
#pragma unroll
        for (int j = 0; j < 8; j++)
            *(__half2*)(row + 8 * j + colq) = __floats2half2_rn(acc[j][2], acc[j][3]);
    }
}

// ---------------------------------------------------------------------------
// Gather + bias + stats + transpose. 512 threads = 16 warps; warp handles
// 4 faces (R10 parallelism: 50K warps chip-wide); tile = 64 faces.
// Writes y_t[b][c][f] fp16 (coalesced 128B rows).
__global__ __launch_bounds__(512) void gather_kernel(const int* __restrict__ ring,
                                                     const float* __restrict__ bias,
                                                     float* __restrict__ dummy) {
    __shared__ float tile[64][65];      // y fp32 [f_local][c]
    __shared__ float ssum[CC];
    __shared__ float ssq[CC];

    const int t = threadIdx.x;
    const int wid = t >> 5, lane = t & 31;
    const int b = blockIdx.y;
    const int f0 = blockIdx.x * 64;

    if (t < CC) { ssum[t] = 0.f; ssq[t] = 0.f; }
    __syncthreads();

    const __half2* gb = (const __half2*)(g_buf + (size_t)b * (FD * CC));
    const float bias0 = bias[2 * lane];
    const float bias1 = bias[2 * lane + 1];
    float s0 = 0.f, s1 = 0.f, q0 = 0.f, q1 = 0.f;

    // prefetch all 4 ring-index vectors (batched index-load latency)
    int myidx[4];
#pragma unroll
    for (int i = 0; i < 4; i++) {
        int f = f0 + wid * 4 + i;
        myidx[i] = 0;
        if (f < FD && lane < KN) {
            int v = ring[((long long)(b * FD + f)) * KN + lane];
            if ((unsigned)v < (unsigned)FD) myidx[i] = v;   // defensive
        }
    }

#pragma unroll
    for (int i = 0; i < 4; i++) {
        int f = f0 + wid * 4 + i;
        if (f >= FD) continue;
        float accx = 0.f, accy = 0.f;
#pragma unroll
        for (int k = 0; k < KN; k++) {
            int idx = __shfl_sync(0xffffffffu, myidx[i], k);
            float2 v = __half22float2(gb[(size_t)idx * 32 + lane]);
            accx += v.x;
            accy += v.y;
        }
        float y0 = accx + bias0;
        float y1 = accy + bias1;
        tile[wid * 4 + i][2 * lane]     = y0;
        tile[wid * 4 + i][2 * lane + 1] = y1;
        s0 += y0; q0 += y0 * y0;
        s1 += y1; q1 += y1 * y1;
    }

    atomicAdd(&ssum[2 * lane],     s0);
    atomicAdd(&ssum[2 * lane + 1], s1);
    atomicAdd(&ssq[2 * lane],      q0);
    atomicAdd(&ssq[2 * lane + 1],  q1);
    __syncthreads();

    // transposed coalesced fp16 write: warp w covers c = w, w+16, w+32, w+48
    {
        const int ff = f0 + 2 * lane;
        if (ff + 1 < FD) {
#pragma unroll
            for (int cc = 0; cc < 4; cc++) {
                int c = wid + 16 * cc;
                __half2 hv = __floats2half2_rn(tile[2 * lane][c],
                                               tile[2 * lane + 1][c]);
                *(__half2*)(g_yt + ((size_t)(b * CC + c)) * FD + ff) = hv;
            }
        }
    }

    if (t < CC) {
        atomicAdd(&g_sum[t], ssum[t]);
        atomicAdd(&g_sq[t],  ssq[t]);
    }
}

// ---------------------------------------------------------------------------
// Streaming norm: read y_t fp16 [b][c][f], normalize+ReLU, write out fp32.
// Thread handles 8 consecutive faces: 1 LDG.128 -> 8 FMA/ReLU -> 2 STG.128.
__global__ __launch_bounds__(256) void norm_kernel(const float* __restrict__ gamma,
                                                   const float* __restrict__ beta,
                                                   float* __restrict__ out) {
    const int id = blockIdx.x * 256 + threadIdx.x;
    const int b = id / (CC * NORM_CHUNKS);
    const int rem = id % (CC * NORM_CHUNKS);
    const int c = rem / NORM_CHUNKS;
    const int f0 = (rem % NORM_CHUNKS) * 8;

    const float inv_n = 1.0f / (float)(BB * FD);
    const float mean = g_sum[c] * inv_n;
    const float var  = g_sq[c] * inv_n - mean * mean;
    const float sc = gamma[c] * rsqrtf(var + BN_EPS);
    const float sh = beta[c] - mean * sc;

    const size_t base = ((size_t)(b * CC + c)) * FD + f0;
    uint4 v = *(const uint4*)(g_yt + base);
    const __half2* hp = (const __half2*)&v;
    float4 o0, o1;
    float2 p;
    p = __half22float2(hp[0]);
    o0.x = fmaxf(fmaf(p.x, sc, sh), 0.f); o0.y = fmaxf(fmaf(p.y, sc, sh), 0.f);
    p = __half22float2(hp[1]);
    o0.z = fmaxf(fmaf(p.x, sc, sh), 0.f); o0.w = fmaxf(fmaf(p.y, sc, sh), 0.f);
    p = __half22float2(hp[2]);
    o1.x = fmaxf(fmaf(p.x, sc, sh), 0.f); o1.y = fmaxf(fmaf(p.y, sc, sh), 0.f);
    p = __half22float2(hp[3]);
    o1.z = fmaxf(fmaf(p.x, sc, sh), 0.f); o1.w = fmaxf(fmaf(p.y, sc, sh), 0.f);
    ((float4*)(out + base))[0] = o0;
    ((float4*)(out + base))[1] = o1;
}

// ---------------------------------------------------------------------------
extern "C" void kernel_launch(void* const* d_in, const int* in_sizes, int n_in,
                              void* d_out, int out_size) {
    const float* fea   = (const float*)d_in[0];      // [B, C_in, F]
    const int*   ring  = (const int*)d_in[1];        // [B, F, K] int32
    const float* W     = (const float*)d_in[2];      // [C_out, C_in]
    const float* bias  = (const float*)d_in[3];      // [C_out]
    const float* gamma = (const float*)d_in[4];      // [C_out]
    const float* beta  = (const float*)d_in[5];      // [C_out]
    float*       out   = (float*)d_out;              // [B, C_out, F]

    dim3 gg(GEMM_TILES, BB);
    gemm_kernel<<<gg, 256>>>(fea, W);

    dim3 gt(GTILES, BB);
    gather_kernel<<<gt, 512>>>(ring, bias, out);

    norm_kernel<<<(BB * CC * NORM_CHUNKS) / 256, 256>>>(gamma, beta, out);
}

// round 16
// speedup vs baseline: 1.2049x; 1.1187x over previous
#include <cuda_runtime.h>
#include <cuda_fp16.h>
#include <cstdint>

#define BB 4
#define CC 64
#define FD 50000
#define KN 16
#define BN_EPS 1e-5f

#define GEMM_TILES 391      // (FD+127)/128
#define GTILES32 1563       // (FD+31)/32
#define NORM_CHUNKS 6250    // FD/8

__device__ __half g_buf[BB * FD * CC];   // g[b][f][o] fp16
__device__ __half g_yt[BB * CC * FD];    // y_t[b][c][f] fp16
__device__ float g_sum[CC];
__device__ float g_sq[CC];

// ---------------------------------------------------------------------------
__device__ __forceinline__ uint32_t smem_u32(const void* p) {
    uint32_t a;
    asm("{ .reg .u64 t; cvta.to.shared.u64 t, %1; cvt.u32.u64 %0, t; }"
        : "=r"(a) : "l"(p));
    return a;
}
__device__ __forceinline__ void ldsm_x4(uint32_t& r0, uint32_t& r1,
                                        uint32_t& r2, uint32_t& r3, uint32_t addr) {
    asm volatile("ldmatrix.sync.aligned.m8n8.x4.shared.b16 {%0,%1,%2,%3}, [%4];"
                 : "=r"(r0), "=r"(r1), "=r"(r2), "=r"(r3) : "r"(addr));
}
__device__ __forceinline__ void ldsm_x4_trans(uint32_t& r0, uint32_t& r1,
                                              uint32_t& r2, uint32_t& r3, uint32_t addr) {
    asm volatile("ldmatrix.sync.aligned.m8n8.x4.trans.shared.b16 {%0,%1,%2,%3}, [%4];"
                 : "=r"(r0), "=r"(r1), "=r"(r2), "=r"(r3) : "r"(addr));
}
__device__ __forceinline__ void mma16816(float* c, uint32_t a0, uint32_t a1,
                                         uint32_t a2, uint32_t a3,
                                         uint32_t b0, uint32_t b1) {
    asm volatile(
        "mma.sync.aligned.m16n8k16.row.col.f32.f16.f16.f32 "
        "{%0,%1,%2,%3}, {%4,%5,%6,%7}, {%8,%9}, {%0,%1,%2,%3};"
        : "+f"(c[0]), "+f"(c[1]), "+f"(c[2]), "+f"(c[3])
        : "r"(a0), "r"(a1), "r"(a2), "r"(a3), "r"(b0), "r"(b1));
}

// ---------------------------------------------------------------------------
// GEMM via mma.sync (R10, proven): D[128f][64o] = A[128f][64c] * W[64o][64c]^T
#define SPA 136  // sA row stride halves (272B == 16 mod 128)
#define SPB 72   // sB row stride halves (144B == 16 mod 128)
__global__ __launch_bounds__(256)
void gemm_kernel(const float* __restrict__ fea, const float* __restrict__ W) {
    __shared__ __align__(16) __half sA[64 * SPA];  // [c][f]
    __shared__ __align__(16) __half sB[64 * SPB];  // [o][c]

    const int b = blockIdx.y;
    const int f0 = blockIdx.x * 128;
    const int t = threadIdx.x;
    const int wid = t >> 5, lane = t & 31;

    // stats zeroing: race-free (kernel boundary orders gemm before gather)
    if (f0 == 0 && b == 0 && t < CC) { g_sum[t] = 0.f; g_sq[t] = 0.f; }

    // stage B = W [64o][64c] fp16 padded rows
    {
        const int o = t >> 2, q = t & 3;
        union { __half2 h2[8]; uint4 u[2]; } pk;
#pragma unroll
        for (int i = 0; i < 4; i++) {
            float4 wv = *(const float4*)(W + o * CC + q * 16 + 4 * i);
            pk.h2[2 * i]     = __floats2half2_rn(wv.x, wv.y);
            pk.h2[2 * i + 1] = __floats2half2_rn(wv.z, wv.w);
        }
        uint4* dst = (uint4*)(sB + o * SPB + q * 16);
        dst[0] = pk.u[0];
        dst[1] = pk.u[1];
    }
    // stage A = fea tile [64c][128f] fp16 as-is
    const float* feab = fea + (size_t)b * (CC * FD);
    const int nv = min(128, FD - f0);
    {
        const int c = t >> 2, q = t & 3;
        const float* src = feab + c * FD + f0 + q * 32;
        __half* dstrow = sA + c * SPA + q * 32;
#pragma unroll
        for (int i = 0; i < 8; i++) {
            float4 v = make_float4(0.f, 0.f, 0.f, 0.f);
            if (q * 32 + 4 * i + 3 < nv) v = *(const float4*)(src + 4 * i);
            union { __half2 h2[2]; unsigned long long u; } pk;
            pk.h2[0] = __floats2half2_rn(v.x, v.y);
            pk.h2[1] = __floats2half2_rn(v.z, v.w);
            *(unsigned long long*)(dstrow + 4 * i) = pk.u;
        }
    }
    __syncthreads();

    const uint32_t aBase = smem_u32(sA);
    const uint32_t bBase = smem_u32(sB);
    const int m0 = wid * 16;
    const int g = lane >> 3, r = lane & 7;
    const uint32_t aKoff = (g >> 1) * 8 + r;
    const uint32_t aMcol = m0 + (g & 1) * 8;
    const uint32_t bRowOff = (lane >> 4) * 8 + (lane & 7);
    const uint32_t bColOff = ((lane >> 3) & 1) * 8;

    float acc[8][4];
#pragma unroll
    for (int j = 0; j < 8; j++)
#pragma unroll
        for (int m = 0; m < 4; m++) acc[j][m] = 0.f;

#pragma unroll
    for (int kk = 0; kk < 4; kk++) {
        uint32_t a0, a1, a2, a3;
        ldsm_x4_trans(a0, a1, a2, a3,
                      aBase + ((kk * 16 + aKoff) * SPA + aMcol) * 2);
#pragma unroll
        for (int j = 0; j < 4; j++) {
            uint32_t b0, b1, b2, b3;
            ldsm_x4(b0, b1, b2, b3,
                    bBase + ((16 * j + bRowOff) * SPB + kk * 16 + bColOff) * 2);
            mma16816(acc[2 * j],     a0, a1, a2, a3, b0, b1);
            mma16816(acc[2 * j + 1], a0, a1, a2, a3, b2, b3);
        }
    }

    const int fr = f0 + m0 + (lane >> 2);
    const int colq = 2 * (lane & 3);
    __half* gb = g_buf + (size_t)b * (FD * CC);
    if (fr < FD) {
        __half* row = gb + (size_t)fr * CC;
#pragma unroll
        for (int j = 0; j < 8; j++)
            *(__half2*)(row + 8 * j + colq) = __floats2half2_rn(acc[j][0], acc[j][1]);
    }
    if (fr + 8 < FD) {
        __half* row = gb + (size_t)(fr + 8) * CC;
#pragma unroll
        for (int j = 0; j < 8; j++)
            *(__half2*)(row + 8 * j + colq) = __floats2half2_rn(acc[j][2], acc[j][3]);
    }
}

// ---------------------------------------------------------------------------
// Gather: R10's EXACT shape (256 thr, 8 warps x 4 faces, 32-face tile,
// fp32 smem tile). Only the epilogue differs: transposed fp16 write to
// y_t[b][c][f] (64B coalesced segments per half-warp).
__global__ __launch_bounds__(256) void gather_kernel(const int* __restrict__ ring,
                                                     const float* __restrict__ bias) {
    __shared__ float tile[32][65];      // [f_local][c], padded
    __shared__ float ssum[CC];
    __shared__ float ssq[CC];

    const int t = threadIdx.x;
    if (t < CC) { ssum[t] = 0.f; ssq[t] = 0.f; }
    __syncthreads();

    const int b = blockIdx.y;
    const int f0 = blockIdx.x * 32;
    const int wid = t >> 5, lane = t & 31;
    const __half2* gb = (const __half2*)(g_buf + (size_t)b * (FD * CC));
    const float bias0 = bias[2 * lane];
    const float bias1 = bias[2 * lane + 1];

    float s0 = 0.f, s1 = 0.f, q0 = 0.f, q1 = 0.f;

#pragma unroll
    for (int i = 0; i < 4; i++) {
        int f = f0 + wid * 4 + i;               // warp-uniform
        if (f >= FD) continue;
        const int* rp = ring + ((long long)(b * FD + f)) * KN;
        int myidx = (lane < KN) ? rp[lane] : 0;
        if ((unsigned)myidx >= (unsigned)FD) myidx = 0;   // defensive
        float accx = 0.f, accy = 0.f;
#pragma unroll
        for (int k = 0; k < KN; k++) {
            int idx = __shfl_sync(0xffffffffu, myidx, k);
            float2 v = __half22float2(gb[(size_t)idx * 32 + lane]);
            accx += v.x;
            accy += v.y;
        }
        float y0 = accx + bias0;
        float y1 = accy + bias1;
        tile[wid * 4 + i][2 * lane]     = y0;
        tile[wid * 4 + i][2 * lane + 1] = y1;
        s0 += y0; q0 += y0 * y0;
        s1 += y1; q1 += y1 * y1;
    }

    atomicAdd(&ssum[2 * lane],     s0);
    atomicAdd(&ssum[2 * lane + 1], s1);
    atomicAdd(&ssq[2 * lane],      q0);
    atomicAdd(&ssq[2 * lane + 1],  q1);
    __syncthreads();

    // transposed fp16 write: warp covers c = wid*8 .. wid*8+7; 16 lanes per
    // c-row write 64B contiguous (half2 each).
    {
        const int fi = 2 * (lane & 15);
        const int ff = f0 + fi;
        const int csub = lane >> 4;             // 0 or 1
        if (ff + 1 < FD) {
#pragma unroll
            for (int cc = 0; cc < 4; cc++) {
                int c = wid * 8 + cc * 2 + csub;
                __half2 hv = __floats2half2_rn(tile[fi][c], tile[fi + 1][c]);
                *(__half2*)(g_yt + ((size_t)(b * CC + c)) * FD + ff) = hv;
            }
        }
    }

    if (t < CC) {
        atomicAdd(&g_sum[t], ssum[t]);
        atomicAdd(&g_sq[t],  ssq[t]);
    }
}

// ---------------------------------------------------------------------------
// Streaming norm: read y_t fp16 [b][c][f], normalize+ReLU, write out fp32.
// Thread handles 8 consecutive faces: 1 LDG.128 -> 8 FMA/ReLU -> 2 STG.128.
__global__ __launch_bounds__(256) void norm_kernel(const float* __restrict__ gamma,
                                                   const float* __restrict__ beta,
                                                   float* __restrict__ out) {
    const int id = blockIdx.x * 256 + threadIdx.x;
    const int b = id / (CC * NORM_CHUNKS);
    const int rem = id % (CC * NORM_CHUNKS);
    const int c = rem / NORM_CHUNKS;
    const int f0 = (rem % NORM_CHUNKS) * 8;

    const float inv_n = 1.0f / (float)(BB * FD);
    const float mean = g_sum[c] * inv_n;
    const float var  = g_sq[c] * inv_n - mean * mean;
    const float sc = gamma[c] * rsqrtf(var + BN_EPS);
    const float sh = beta[c] - mean * sc;

    const size_t base = ((size_t)(b * CC + c)) * FD + f0;
    uint4 v = *(const uint4*)(g_yt + base);
    const __half2* hp = (const __half2*)&v;
    float4 o0, o1;
    float2 p;
    p = __half22float2(hp[0]);
    o0.x = fmaxf(fmaf(p.x, sc, sh), 0.f); o0.y = fmaxf(fmaf(p.y, sc, sh), 0.f);
    p = __half22float2(hp[1]);
    o0.z = fmaxf(fmaf(p.x, sc, sh), 0.f); o0.w = fmaxf(fmaf(p.y, sc, sh), 0.f);
    p = __half22float2(hp[2]);
    o1.x = fmaxf(fmaf(p.x, sc, sh), 0.f); o1.y = fmaxf(fmaf(p.y, sc, sh), 0.f);
    p = __half22float2(hp[3]);
    o1.z = fmaxf(fmaf(p.x, sc, sh), 0.f); o1.w = fmaxf(fmaf(p.y, sc, sh), 0.f);
    ((float4*)(out + base))[0] = o0;
    ((float4*)(out + base))[1] = o1;
}

// ---------------------------------------------------------------------------
extern "C" void kernel_launch(void* const* d_in, const int* in_sizes, int n_in,
                              void* d_out, int out_size) {
    const float* fea   = (const float*)d_in[0];      // [B, C_in, F]
    const int*   ring  = (const int*)d_in[1];        // [B, F, K] int32
    const float* W     = (const float*)d_in[2];      // [C_out, C_in]
    const float* bias  = (const float*)d_in[3];      // [C_out]
    const float* gamma = (const float*)d_in[4];      // [C_out]
    const float* beta  = (const float*)d_in[5];      // [C_out]
    float*       out   = (float*)d_out;              // [B, C_out, F]

    dim3 gg(GEMM_TILES, BB);
    gemm_kernel<<<gg, 256>>>(fea, W);

    dim3 gt(GTILES32, BB);
    gather_kernel<<<gt, 256>>>(ring, bias);

    norm_kernel<<<(BB * CC * NORM_CHUNKS) / 256, 256>>>(gamma, beta, out);
}